// round 4
// baseline (speedup 1.0000x reference)
#include <cuda_runtime.h>
#include <cuda_bf16.h>
#include <math.h>

#define NN 4096
#define IN_DIM 1433
#define HID 64
#define OUT_DIM 7
#define MAXDEG 160
#define SCAD_A 3.7f
#define LAMW ((float)(1.0/0.9 - 1.0))
#define K_STEPS 10
#define KT 32
#define NTILE ((IN_DIM + KT - 1) / KT)   // 45
#define PBLK 148                          // persistent grid size
#define PTHR 256

// ---------------- device globals (no allocation allowed) ----------------
__device__ float g_H[NN * HID];
__device__ float g_NdA[NN * 8];          // node pack ping: {Fn[0..6], sq}
__device__ float g_NdB[NN * 8];          // node pack pong
__device__ float g_rD[NN];
__device__ float g_D[NN];
__device__ int   g_cols[NN * MAXDEG];
__device__ int   g_deg[NN];
__device__ unsigned g_bar_cnt;
__device__ unsigned g_bar_epoch;

typedef unsigned long long ull;

// ---- packed fp32x2 helpers ----
__device__ __forceinline__ ull pack_dup(float v) {
    ull r; asm("mov.b64 %0, {%1, %1};" : "=l"(r) : "f"(v)); return r;
}
__device__ __forceinline__ void fma2(ull& d, ull a, ull b) {
    asm("fma.rn.f32x2 %0, %1, %2, %0;" : "+l"(d) : "l"(a), "l"(b));
}
__device__ __forceinline__ void unpack2(ull p, float& lo, float& hi) {
    asm("mov.b64 {%0, %1}, %2;" : "=f"(lo), "=f"(hi) : "l"(p));
}

// ============================================================================
// Kernel 1: adjacency build (phase A, full grid) then MLP layer 1 (phase B)
// grid 128 x 512 threads
// ============================================================================
__global__ __launch_bounds__(512, 1)
void fused_build_mlp1(const float* __restrict__ A,
                      const float* __restrict__ X,
                      const float* __restrict__ w1,
                      const float* __restrict__ b1) {
    __shared__ __align__(16) float Xs[2][KT][34];
    __shared__ __align__(16) float Ws[2][KT][HID];
    int tid = threadIdx.x;
    int warp = tid >> 5, lane = tid & 31;

    // ---------------- phase A: adjacency (32 rows per block) ----------------
    {
        int rbase = blockIdx.x * 32 + warp * 2;
        for (int rr = 0; rr < 2; rr++) {
            int r = rbase + rr;
            const float4* row4 = (const float4*)(A + (size_t)r * NN);
            int* cols = g_cols + (size_t)r * MAXDEG;
            int cnt = 0;
            for (int c0 = 0; c0 < NN / 4; c0 += 32) {
                float4 v = row4[c0 + lane];
                int cb = (c0 + lane) * 4;
                #pragma unroll
                for (int e = 0; e < 4; e++) {
                    float f = (e == 0) ? v.x : (e == 1) ? v.y : (e == 2) ? v.z : v.w;
                    bool nz = (f != 0.0f);
                    unsigned m = __ballot_sync(0xffffffffu, nz);
                    if (nz) {
                        int pos = cnt + __popc(m & ((1u << lane) - 1u));
                        if (pos < MAXDEG) cols[pos] = cb + e;
                    }
                    cnt += __popc(m);
                }
            }
            if (lane == 0) {
                g_deg[r] = cnt < MAXDEG ? cnt : MAXDEG;
                float D = (float)cnt + 1.0f;
                g_D[r] = D;
                g_rD[r] = 1.0f / sqrtf(D);
            }
        }
    }
    __syncthreads();

    // ---------------- phase B: mlp1, k-split into 2 groups of 256 ----------
    int g  = tid >> 8;          // 0 / 1
    int gt = tid & 255;
    int m0 = blockIdx.x * 32;
    int t0 = g == 0 ? 0 : 23;
    int t1 = g == 0 ? 23 : NTILE;
    int tx = gt & 15;           // col group: cols tx*4..+3
    int ty = gt >> 4;           // row pair: rows ty*2, ty*2+1
    int barid = 1 + g;

    ull acc[2][2] = {{0ull, 0ull}, {0ull, 0ull}};
    float xr[4], wr[8];

    // prefetch tile t0
    {
        int tk = t0 * KT;
        #pragma unroll
        for (int j = 0; j < 4; j++) {
            int idx = gt + j * 256;
            int k = tk + (idx & 31), m = idx >> 5;
            xr[j] = (k < IN_DIM) ? X[(size_t)(m0 + m) * IN_DIM + k] : 0.0f;
        }
        #pragma unroll
        for (int j = 0; j < 8; j++) {
            int idx = gt + j * 256;
            int k = tk + (idx >> 6), n = idx & 63;
            wr[j] = (k < IN_DIM) ? w1[(size_t)k * HID + n] : 0.0f;
        }
    }

    for (int t = t0; t < t1; t++) {
        asm volatile("bar.sync %0, %1;" :: "r"(barid), "r"(256) : "memory");
        #pragma unroll
        for (int j = 0; j < 4; j++) {
            int idx = gt + j * 256;
            Xs[g][idx & 31][idx >> 5] = xr[j];
        }
        #pragma unroll
        for (int j = 0; j < 8; j++) {
            int idx = gt + j * 256;
            Ws[g][idx >> 6][idx & 63] = wr[j];
        }
        asm volatile("bar.sync %0, %1;" :: "r"(barid), "r"(256) : "memory");

        if (t + 1 < t1) {
            int tk = (t + 1) * KT;
            #pragma unroll
            for (int j = 0; j < 4; j++) {
                int idx = gt + j * 256;
                int k = tk + (idx & 31), m = idx >> 5;
                xr[j] = (k < IN_DIM) ? X[(size_t)(m0 + m) * IN_DIM + k] : 0.0f;
            }
            #pragma unroll
            for (int j = 0; j < 8; j++) {
                int idx = gt + j * 256;
                int k = tk + (idx >> 6), n = idx & 63;
                wr[j] = (k < IN_DIM) ? w1[(size_t)k * HID + n] : 0.0f;
            }
        }

        #pragma unroll
        for (int k = 0; k < KT; k++) {
            ull a01 = *(const ull*)&Xs[g][k][ty * 2];
            float a0, a1; unpack2(a01, a0, a1);
            ull da0 = pack_dup(a0), da1 = pack_dup(a1);
            ulonglong2 bb = *(const ulonglong2*)&Ws[g][k][tx * 4];
            fma2(acc[0][0], da0, bb.x);
            fma2(acc[0][1], da0, bb.y);
            fma2(acc[1][0], da1, bb.x);
            fma2(acc[1][1], da1, bb.y);
        }
    }

    // combine the two k-partials: group0 -> smem, group1 adds + writes H
    __syncthreads();
    if (g == 0) {
        float* buf = &Ws[0][0][0];   // 2048 floats, exactly 256 threads * 8
        #pragma unroll
        for (int m = 0; m < 2; m++)
            #pragma unroll
            for (int p = 0; p < 2; p++) {
                float lo, hi; unpack2(acc[m][p], lo, hi);
                buf[gt * 8 + m * 4 + p * 2]     = lo;
                buf[gt * 8 + m * 4 + p * 2 + 1] = hi;
            }
    }
    __syncthreads();
    if (g == 1) {
        const float* buf = &Ws[0][0][0];
        float4 bv = *(const float4*)&b1[tx * 4];
        float bias[4] = {bv.x, bv.y, bv.z, bv.w};
        #pragma unroll
        for (int m = 0; m < 2; m++) {
            int row = m0 + ty * 2 + m;
            #pragma unroll
            for (int p = 0; p < 2; p++) {
                float lo, hi; unpack2(acc[m][p], lo, hi);
                lo += buf[gt * 8 + m * 4 + p * 2];
                hi += buf[gt * 8 + m * 4 + p * 2 + 1];
                g_H[(size_t)row * HID + tx * 4 + p * 2]     = fmaxf(lo + bias[p * 2], 0.0f);
                g_H[(size_t)row * HID + tx * 4 + p * 2 + 1] = fmaxf(hi + bias[p * 2 + 1], 0.0f);
            }
        }
    }
}

// ============================================================================
// Kernel 2: persistent — mlp2 (F0) + 10 diffusion iterations with global barrier
// grid 148 x 256, ~170KB dynamic smem (forces 1 block/SM => all resident)
// ============================================================================

// smem layout offsets in bytes
#define SO_NDS     0                       // float[32768] staged node packs
#define SO_COLS    131072                  // int[4480] remapped edge lists
#define SO_UNIQ    148992                  // int[4096] unique-neighbor global ids
#define SO_F0      165376                  // float[28*8]
#define SO_DEG     166272                  // int[28]
#define SO_RD      166384                  // float[28]
#define SO_DD      166496                  // float[28]
#define SO_ROWLOC  166608                  // int[28]
#define SO_W2      166720                  // float[448]
#define SO_B2      168512                  // float[7]
#define SO_BITMAP  168540                  // uint[128]
#define SO_BASE    169052                  // uint[129]
#define SO_EPOCH0  169568                  // uint
#define SMEM_PERS  169600

__device__ __forceinline__ void bar_arrive_wait(unsigned target_epoch) {
    __syncthreads();
    if (threadIdx.x == 0) {
        unsigned old;
        asm volatile("atom.add.acq_rel.gpu.u32 %0, [%1], %2;"
                     : "=r"(old) : "l"(&g_bar_cnt), "r"(1u) : "memory");
        if (old == target_epoch * (unsigned)PBLK - 1u) {
            asm volatile("st.release.gpu.u32 [%0], %1;"
                         :: "l"(&g_bar_epoch), "r"(target_epoch) : "memory");
        } else {
            unsigned e;
            do {
                asm volatile("ld.acquire.gpu.u32 %0, [%1];"
                             : "=r"(e) : "l"(&g_bar_epoch) : "memory");
            } while ((int)(e - target_epoch) < 0);
        }
    }
    __syncthreads();
}

__global__ __launch_bounds__(PTHR, 1)
void persistent_iter(const float* __restrict__ w2,
                     const float* __restrict__ b2,
                     const float* __restrict__ lg0p,
                     const float* __restrict__ rawp,
                     float* __restrict__ out) {
    extern __shared__ char smem[];
    float*    NdS    = (float*)(smem + SO_NDS);
    int*      colsS  = (int*)(smem + SO_COLS);
    int*      uniqS  = (int*)(smem + SO_UNIQ);
    float*    F0s    = (float*)(smem + SO_F0);
    int*      degS   = (int*)(smem + SO_DEG);
    float*    rDs    = (float*)(smem + SO_RD);
    float*    Ds     = (float*)(smem + SO_DD);
    int*      rowloc = (int*)(smem + SO_ROWLOC);
    float*    w2s    = (float*)(smem + SO_W2);
    float*    b2s    = (float*)(smem + SO_B2);
    unsigned* bitmap = (unsigned*)(smem + SO_BITMAP);
    unsigned* baseS  = (unsigned*)(smem + SO_BASE);
    unsigned* ep0s   = (unsigned*)(smem + SO_EPOCH0);

    int tid = threadIdx.x;
    int bid = blockIdx.x;
    int warp = tid >> 5, lane = tid & 31;

    int cnt   = (bid < 100) ? 28 : 27;
    int start = (bid < 100) ? bid * 28 : 2800 + (bid - 100) * 27;

    // epoch base (robust to graph replays: counters are monotonic)
    if (tid == 0) {
        unsigned e;
        asm volatile("ld.acquire.gpu.u32 %0, [%1];" : "=r"(e) : "l"(&g_bar_epoch) : "memory");
        *ep0s = e;
    }
    // per-thread scalars
    float g0 = expf(__ldcg(lg0p));
    float rr = 1.0f / (1.0f + expf(-__ldcg(rawp)));
    float gk = g0;

    // ---- phase 0a: row metadata + weights + bitmap clear ----
    if (tid < cnt) {
        degS[tid] = g_deg[start + tid];
        rDs[tid]  = g_rD[start + tid];
        Ds[tid]   = g_D[start + tid];
    }
    for (int i = tid; i < HID * OUT_DIM; i += PTHR) w2s[i] = w2[i];
    if (tid < OUT_DIM) b2s[tid] = b2[tid];
    if (tid < 128) bitmap[tid] = 0u;
    __syncthreads();

    // ---- phase 0b: edge load + bitmap mark; mlp2 F0 ----
    for (int idx = tid; idx < cnt * MAXDEG; idx += PTHR) {
        int r = idx / MAXDEG, e = idx - r * MAXDEG;
        if (e < degS[r]) {
            int j = g_cols[(size_t)(start + r) * MAXDEG + e];
            colsS[idx] = j;
            atomicOr(&bitmap[j >> 5], 1u << (j & 31));
        } else colsS[idx] = -1;
    }
    if (tid < cnt) {
        int j = start + tid;
        atomicOr(&bitmap[j >> 5], 1u << (j & 31));
    }
    if (tid < cnt * OUT_DIM) {
        int r = tid / OUT_DIM, o = tid - r * OUT_DIM;
        const float* h = g_H + (size_t)(start + r) * HID;
        float acc = b2s[o];
        #pragma unroll 8
        for (int k = 0; k < HID; k++) acc = fmaf(h[k], w2s[k * OUT_DIM + o], acc);
        F0s[r * 8 + o] = acc;
    }
    __syncthreads();

    // ---- phase 0c: prefix scan of bitmap popcounts ----
    if (tid == 0) {
        unsigned acc = 0;
        for (int w = 0; w < 128; w++) { baseS[w] = acc; acc += __popc(bitmap[w]); }
        baseS[128] = acc;
    }
    __syncthreads();

    // ---- phase 0d: unique list, remap edges, row locals, Nd seed ----
    if (tid < 128) {
        unsigned w = bitmap[tid];
        unsigned b = baseS[tid];
        while (w) {
            int bpos = __ffs(w) - 1;
            uniqS[b++] = tid * 32 + bpos;
            w &= w - 1;
        }
    }
    for (int idx = tid; idx < cnt * MAXDEG; idx += PTHR) {
        int j = colsS[idx];
        if (j >= 0)
            colsS[idx] = baseS[j >> 5] + __popc(bitmap[j >> 5] & ((1u << (j & 31)) - 1u));
    }
    if (tid < cnt) {
        int j = start + tid;
        rowloc[tid] = baseS[j >> 5] + __popc(bitmap[j >> 5] & ((1u << (j & 31)) - 1u));
        // Nd seed from F0
        float rd = rDs[tid];
        float fn[7], ss = 0.0f;
        #pragma unroll
        for (int c = 0; c < 7; c++) {
            fn[c] = F0s[tid * 8 + c] * rd;
            ss = fmaf(fn[c], fn[c], ss);
        }
        float4* dst = (float4*)(g_NdA + (size_t)j * 8);
        __stcg(dst,     make_float4(fn[0], fn[1], fn[2], fn[3]));
        __stcg(dst + 1, make_float4(fn[4], fn[5], fn[6], ss));
    }
    __syncthreads();
    unsigned ep0 = *ep0s;
    unsigned nuniq = baseS[128];

    bar_arrive_wait(ep0 + 1);

    // ---- 10 iterations ----
    for (int k = 0; k < K_STEPS; k++) {
        const float* Ndin  = (k & 1) ? g_NdB : g_NdA;
        float*       Ndout = (k & 1) ? g_NdA : g_NdB;

        // stage unique neighbors into smem
        for (unsigned t = tid; t < nuniq; t += PTHR) {
            int j = uniqS[t];
            const float4* p = (const float4*)(Ndin + (size_t)j * 8);
            float4 v0 = __ldcg(p), v1 = __ldcg(p + 1);
            *(float4*)&NdS[t * 8]     = v0;
            *(float4*)&NdS[t * 8 + 4] = v1;
        }
        __syncthreads();

        float lam  = gk / SCAD_A;
        float alam = SCAD_A * lam;

        for (int r = warp; r < cnt; r += (PTHR / 32)) {
            int iloc = rowloc[r];
            float4 f0 = *(const float4*)&NdS[iloc * 8];
            float4 f1 = *(const float4*)&NdS[iloc * 8 + 4];
            float fni[7] = {f0.x, f0.y, f0.z, f0.w, f1.x, f1.y, f1.z};
            float sqi = f1.w;
            float rdi = rDs[r];
            int dg = degS[r];
            const int* cl = colsS + r * MAXDEG;

            float s = 0.0f;
            float acc[7] = {0.f, 0.f, 0.f, 0.f, 0.f, 0.f, 0.f};
            for (int e = lane; e < dg; e += 32) {
                int jl = cl[e];
                float4 a0 = *(const float4*)&NdS[jl * 8];
                float4 a1 = *(const float4*)&NdS[jl * 8 + 4];
                float dot = fni[0] * a0.x + fni[1] * a0.y + fni[2] * a0.z + fni[3] * a0.w
                          + fni[4] * a1.x + fni[5] * a1.y + fni[6] * a1.z;
                float Z = fmaxf(sqi + a1.w - 2.0f * dot, 0.0f);
                float y = sqrtf(Z);
                float w;
                if (y <= lam)        w = 1.0f;
                else if (y <= alam)  w = (alam - y) / ((SCAD_A - 1.0f) * fmaxf(y, 1e-12f));
                else                 w = 0.0f;
                s += w;
                acc[0] = fmaf(w, a0.x, acc[0]);
                acc[1] = fmaf(w, a0.y, acc[1]);
                acc[2] = fmaf(w, a0.z, acc[2]);
                acc[3] = fmaf(w, a0.w, acc[3]);
                acc[4] = fmaf(w, a1.x, acc[4]);
                acc[5] = fmaf(w, a1.y, acc[5]);
                acc[6] = fmaf(w, a1.z, acc[6]);
            }
            #pragma unroll
            for (int off = 16; off > 0; off >>= 1) {
                s += __shfl_down_sync(0xffffffffu, s, off);
                #pragma unroll
                for (int c = 0; c < 7; c++)
                    acc[c] += __shfl_down_sync(0xffffffffu, acc[c], off);
            }
            if (lane == 0) {
                float Q = s / Ds[r] + LAMW;
                float invQ = 1.0f / Q;
                float f[7];
                #pragma unroll
                for (int c = 0; c < 7; c++)
                    f[c] = (rdi * acc[c] + LAMW * F0s[r * 8 + c]) * invQ;
                if (k == K_STEPS - 1) {
                    float* o = out + (size_t)(start + r) * OUT_DIM;
                    #pragma unroll
                    for (int c = 0; c < 7; c++) o[c] = f[c];
                } else {
                    float fn[7], ss = 0.0f;
                    #pragma unroll
                    for (int c = 0; c < 7; c++) {
                        fn[c] = f[c] * rdi;
                        ss = fmaf(fn[c], fn[c], ss);
                    }
                    float4* dst = (float4*)(Ndout + (size_t)(start + r) * 8);
                    __stcg(dst,     make_float4(fn[0], fn[1], fn[2], fn[3]));
                    __stcg(dst + 1, make_float4(fn[4], fn[5], fn[6], ss));
                }
            }
        }
        gk *= rr;
        if (k < K_STEPS - 1) bar_arrive_wait(ep0 + 2 + (unsigned)k);
    }
}

// ---------------- launch ----------------
extern "C" void kernel_launch(void* const* d_in, const int* in_sizes, int n_in,
                              void* d_out, int out_size) {
    const float *A = nullptr, *X = nullptr, *w1 = nullptr, *b1 = nullptr,
                *w2 = nullptr, *b2 = nullptr, *lg0 = nullptr, *raw = nullptr;
    for (int t = 0; t < n_in; t++) {
        int sz = in_sizes[t];
        const float* p = (const float*)d_in[t];
        if      (sz == NN * NN)        A  = p;
        else if (sz == NN * IN_DIM)    X  = p;
        else if (sz == IN_DIM * HID)   w1 = p;
        else if (sz == HID)            b1 = p;
        else if (sz == HID * OUT_DIM)  w2 = p;
        else if (sz == OUT_DIM)        b2 = p;
        else if (sz == 1) { if (!lg0) lg0 = p; else raw = p; }
    }
    float* out = (float*)d_out;

    static bool attr_done = false;
    if (!attr_done) {
        cudaFuncSetAttribute(persistent_iter,
                             cudaFuncAttributeMaxDynamicSharedMemorySize, SMEM_PERS);
        attr_done = true;
    }

    fused_build_mlp1<<<128, 512>>>(A, X, w1, b1);
    persistent_iter<<<PBLK, PTHR, SMEM_PERS>>>(w2, b2, lg0, raw, out);
}

// round 6
// speedup vs baseline: 1.0624x; 1.0624x over previous
#include <cuda_runtime.h>
#include <cuda_bf16.h>
#include <math.h>

#define NN 4096
#define IN_DIM 1433
#define HID 64
#define OUT_DIM 7
#define MAXDEG 160
#define SCAD_A 3.7f
#define LAMW ((float)(1.0/0.9 - 1.0))
#define K_STEPS 10
#define KT 32
#define NTILE ((IN_DIM + KT - 1) / KT)   // 45

// ---------------- device globals ----------------
__device__ float  g_H[NN * HID];
__device__ float  g_F0[NN * 8];
__device__ float  g_NdA[NN * 8];          // {Fn[0..6], sq} ping
__device__ float  g_NdB[NN * 8];          // pong
__device__ float4 g_meta[NN];             // {rD, D, deg(bits), 0}
__device__ float  g_lam[K_STEPS];
__device__ int    g_cols[NN * MAXDEG];

typedef unsigned long long ull;

__device__ __forceinline__ ull pack_dup(float v) {
    ull r; asm("mov.b64 %0, {%1, %1};" : "=l"(r) : "f"(v)); return r;
}
__device__ __forceinline__ void fma2(ull& d, ull a, ull b) {
    asm("fma.rn.f32x2 %0, %1, %2, %0;" : "+l"(d) : "l"(a), "l"(b));
}
__device__ __forceinline__ void unpack2(ull p, float& lo, float& hi) {
    asm("mov.b64 {%0, %1}, %2;" : "=f"(lo), "=f"(hi) : "l"(p));
}

// ============================================================================
// Kernel 1: block-specialized  —  blocks [0,128): adjacency; [128,256): mlp1
// 256 threads per block
// ============================================================================
__global__ __launch_bounds__(256, 2)
void fused_build_mlp1(const float* __restrict__ A,
                      const float* __restrict__ X,
                      const float* __restrict__ w1,
                      const float* __restrict__ b1) {
    __shared__ __align__(16) ull   Xd[2][KT][33];    // duplicated X: (x,x)
    __shared__ __align__(16) float Wsm[2][KT][HID];
    int tid = threadIdx.x;

    if (blockIdx.x < 128) {
        // ---------------- adjacency: 32 rows per block, 8 warps x 4 rows ----
        int warp = tid >> 5, lane = tid & 31;
        int rbase = blockIdx.x * 32 + warp * 4;
        for (int rr = 0; rr < 4; rr++) {
            int r = rbase + rr;
            const float4* row4 = (const float4*)(A + (size_t)r * NN);
            int* cols = g_cols + (size_t)r * MAXDEG;
            int cnt = 0;
            for (int c0 = 0; c0 < NN / 4; c0 += 32) {
                float4 v = row4[c0 + lane];
                int cb = (c0 + lane) * 4;
                #pragma unroll
                for (int e = 0; e < 4; e++) {
                    float f = (e == 0) ? v.x : (e == 1) ? v.y : (e == 2) ? v.z : v.w;
                    bool nz = (f != 0.0f);
                    unsigned m = __ballot_sync(0xffffffffu, nz);
                    if (nz) {
                        int pos = cnt + __popc(m & ((1u << lane) - 1u));
                        if (pos < MAXDEG) cols[pos] = cb + e;
                    }
                    cnt += __popc(m);
                }
            }
            if (lane == 0) {
                int d = cnt < MAXDEG ? cnt : MAXDEG;
                float D = (float)cnt + 1.0f;
                g_meta[r] = make_float4(1.0f / sqrtf(D), D, __int_as_float(d), 0.0f);
            }
        }
    } else {
        // ---------------- mlp1: 32 rows x 64 cols per block ----------------
        int m0 = (blockIdx.x - 128) * 32;
        int tx = tid & 15;           // col group c0 = tx*4
        int ty = tid >> 4;           // rows ty*2, ty*2+1
        ull acc[2][2] = {{0ull, 0ull}, {0ull, 0ull}};

        // staging fragments (X loaded scalar: IN_DIM=1433 is odd -> rows not
        // 16B aligned, LDG.128 would trap)
        float xr0, xr1, xr2, xr3;    // row xrow, k xk..xk+3
        int xrow = tid >> 3;
        int xk   = (tid & 7) * 4;
        float4 wr[2];                // 2 float4 of w1 (stride 64 floats: aligned)
        const float* xrow_p = X + (size_t)(m0 + xrow) * IN_DIM;
        // prefetch tile 0 (k in [0,32): fully in range)
        {
            xr0 = xrow_p[xk + 0];
            xr1 = xrow_p[xk + 1];
            xr2 = xrow_p[xk + 2];
            xr3 = xrow_p[xk + 3];
            #pragma unroll
            for (int j = 0; j < 2; j++) {
                int f4 = tid + j * 256;
                int k = f4 >> 4, n4 = f4 & 15;
                wr[j] = *(const float4*)(w1 + (size_t)k * HID + n4 * 4);
            }
        }

        for (int t = 0; t < NTILE; t++) {
            int buf = t & 1;
            __syncthreads();
            // store staged fragments
            Xd[buf][xk + 0][xrow] = pack_dup(xr0);
            Xd[buf][xk + 1][xrow] = pack_dup(xr1);
            Xd[buf][xk + 2][xrow] = pack_dup(xr2);
            Xd[buf][xk + 3][xrow] = pack_dup(xr3);
            #pragma unroll
            for (int j = 0; j < 2; j++) {
                int f4 = tid + j * 256;
                int k = f4 >> 4, n4 = f4 & 15;
                *(float4*)&Wsm[buf][k][n4 * 4] = wr[j];
            }
            // prefetch next tile
            if (t + 1 < NTILE) {
                int kt = (t + 1) * KT;
                if (kt + KT <= IN_DIM) {
                    xr0 = xrow_p[kt + xk + 0];
                    xr1 = xrow_p[kt + xk + 1];
                    xr2 = xrow_p[kt + xk + 2];
                    xr3 = xrow_p[kt + xk + 3];
                    #pragma unroll
                    for (int j = 0; j < 2; j++) {
                        int f4 = tid + j * 256;
                        int k = kt + (f4 >> 4), n4 = f4 & 15;
                        wr[j] = *(const float4*)(w1 + (size_t)k * HID + n4 * 4);
                    }
                } else {
                    // tail tile: per-element guards
                    xr0 = (kt + xk + 0 < IN_DIM) ? xrow_p[kt + xk + 0] : 0.0f;
                    xr1 = (kt + xk + 1 < IN_DIM) ? xrow_p[kt + xk + 1] : 0.0f;
                    xr2 = (kt + xk + 2 < IN_DIM) ? xrow_p[kt + xk + 2] : 0.0f;
                    xr3 = (kt + xk + 3 < IN_DIM) ? xrow_p[kt + xk + 3] : 0.0f;
                    #pragma unroll
                    for (int j = 0; j < 2; j++) {
                        int f4 = tid + j * 256;
                        int k = kt + (f4 >> 4), n4 = f4 & 15;
                        if (k < IN_DIM)
                            wr[j] = *(const float4*)(w1 + (size_t)k * HID + n4 * 4);
                        else
                            wr[j] = make_float4(0.f, 0.f, 0.f, 0.f);
                    }
                }
            }
            __syncthreads();
            // compute: 7 instr per k for 8 FMA lanes
            #pragma unroll
            for (int k = 0; k < KT; k++) {
                ull ar0 = Xd[buf][k][ty * 2];
                ull ar1 = Xd[buf][k][ty * 2 + 1];
                ulonglong2 b = *(const ulonglong2*)&Wsm[buf][k][tx * 4];
                fma2(acc[0][0], ar0, b.x);
                fma2(acc[0][1], ar0, b.y);
                fma2(acc[1][0], ar1, b.x);
                fma2(acc[1][1], ar1, b.y);
            }
        }

        float4 bv = *(const float4*)&b1[tx * 4];
        #pragma unroll
        for (int r = 0; r < 2; r++) {
            int row = m0 + ty * 2 + r;
            float o0, o1, o2, o3;
            unpack2(acc[r][0], o0, o1);
            unpack2(acc[r][1], o2, o3);
            float4 res = make_float4(fmaxf(o0 + bv.x, 0.0f), fmaxf(o1 + bv.y, 0.0f),
                                     fmaxf(o2 + bv.z, 0.0f), fmaxf(o3 + bv.w, 0.0f));
            *(float4*)&g_H[(size_t)row * HID + tx * 4] = res;
        }
    }
}

// ============================================================================
// Kernel 2: mlp2 — F0 = H @ w2 + b2; seeds NdA; computes lam table
// ============================================================================
__global__ void mlp2_kernel(const float* __restrict__ w2,
                            const float* __restrict__ b2,
                            const float* __restrict__ lg0p,
                            const float* __restrict__ rawp) {
    __shared__ float sw[HID * OUT_DIM];
    __shared__ float sb[OUT_DIM];
    if (blockIdx.x == 0 && threadIdx.x == 0) {
        float g0 = expf(lg0p[0]);
        float r  = 1.0f / (1.0f + expf(-rawp[0]));
        float gk = g0;
        #pragma unroll
        for (int k = 0; k < K_STEPS; k++) { g_lam[k] = gk / SCAD_A; gk *= r; }
    }
    for (int idx = threadIdx.x; idx < HID * OUT_DIM; idx += blockDim.x)
        sw[idx] = w2[idx];
    if (threadIdx.x < OUT_DIM) sb[threadIdx.x] = b2[threadIdx.x];
    __syncthreads();
    int i = blockIdx.x * blockDim.x + threadIdx.x;
    if (i >= NN) return;
    float acc[OUT_DIM];
    #pragma unroll
    for (int o = 0; o < OUT_DIM; o++) acc[o] = sb[o];
    const float* h = g_H + (size_t)i * HID;
    #pragma unroll 8
    for (int k = 0; k < HID; k++) {
        float hv = h[k];
        #pragma unroll
        for (int o = 0; o < OUT_DIM; o++) acc[o] = fmaf(hv, sw[k * OUT_DIM + o], acc[o]);
    }
    float rd = g_meta[i].x;
    float fn[7], ss = 0.0f;
    #pragma unroll
    for (int o = 0; o < OUT_DIM; o++) {
        g_F0[i * 8 + o] = acc[o];
        fn[o] = acc[o] * rd;
        ss = fmaf(fn[o], fn[o], ss);
    }
    g_F0[i * 8 + 7] = 0.0f;
    float4* nd = (float4*)(g_NdA + i * 8);
    nd[0] = make_float4(fn[0], fn[1], fn[2], fn[3]);
    nd[1] = make_float4(fn[4], fn[5], fn[6], ss);
}

// ============================================================================
// Kernel 3: per-iteration sparse row update — warp per row, 1024 x 128
// ============================================================================
__global__ __launch_bounds__(128)
void row_kernel(int kstep, int last,
                const float* __restrict__ Ndin,
                float* __restrict__ Ndout,
                float* __restrict__ out) {
    int i = (blockIdx.x * 128 + threadIdx.x) >> 5;
    int lane = threadIdx.x & 31;

    float lam = g_lam[kstep];
    float4 meta = g_meta[i];                    // broadcast LDG.128
    float rdi = meta.x, Di = meta.y;
    int deg = __float_as_int(meta.z);
    const float4* ndi = (const float4*)(Ndin + (size_t)i * 8);
    float4 f0 = ndi[0], f1 = ndi[1];
    // lane 0 prefetches F0 row early
    float4 F0a = {0,0,0,0}, F0b = {0,0,0,0};
    if (lane == 0) {
        F0a = *(const float4*)(g_F0 + (size_t)i * 8);
        F0b = *(const float4*)(g_F0 + (size_t)i * 8 + 4);
    }
    float fni[7] = {f0.x, f0.y, f0.z, f0.w, f1.x, f1.y, f1.z};
    float sqi = f1.w;
    float alam = SCAD_A * lam;
    const int* cols = g_cols + (size_t)i * MAXDEG;

    float s = 0.0f;
    float acc[7] = {0.f, 0.f, 0.f, 0.f, 0.f, 0.f, 0.f};
    for (int e = lane; e < deg; e += 32) {
        int j = cols[e];
        const float4* nj = (const float4*)(Ndin + (size_t)j * 8);
        float4 a0 = nj[0], a1 = nj[1];
        float dot = fni[0] * a0.x + fni[1] * a0.y + fni[2] * a0.z + fni[3] * a0.w
                  + fni[4] * a1.x + fni[5] * a1.y + fni[6] * a1.z;
        float Z = fmaxf(sqi + a1.w - 2.0f * dot, 0.0f);
        float y = sqrtf(Z);
        float w;
        if (y <= lam)        w = 1.0f;
        else if (y <= alam)  w = (alam - y) / ((SCAD_A - 1.0f) * fmaxf(y, 1e-12f));
        else                 w = 0.0f;
        s += w;
        acc[0] = fmaf(w, a0.x, acc[0]);
        acc[1] = fmaf(w, a0.y, acc[1]);
        acc[2] = fmaf(w, a0.z, acc[2]);
        acc[3] = fmaf(w, a0.w, acc[3]);
        acc[4] = fmaf(w, a1.x, acc[4]);
        acc[5] = fmaf(w, a1.y, acc[5]);
        acc[6] = fmaf(w, a1.z, acc[6]);
    }
    #pragma unroll
    for (int off = 16; off > 0; off >>= 1) {
        s += __shfl_down_sync(0xffffffffu, s, off);
        #pragma unroll
        for (int c = 0; c < 7; c++)
            acc[c] += __shfl_down_sync(0xffffffffu, acc[c], off);
    }
    if (lane == 0) {
        float Q = s / Di + LAMW;
        float invQ = 1.0f / Q;
        float F0r[7] = {F0a.x, F0a.y, F0a.z, F0a.w, F0b.x, F0b.y, F0b.z};
        float f[7];
        #pragma unroll
        for (int c = 0; c < 7; c++)
            f[c] = (rdi * acc[c] + LAMW * F0r[c]) * invQ;
        if (last) {
            float* o = out + (size_t)i * OUT_DIM;
            #pragma unroll
            for (int c = 0; c < 7; c++) o[c] = f[c];
        } else {
            float fn[7], ss = 0.0f;
            #pragma unroll
            for (int c = 0; c < 7; c++) {
                fn[c] = f[c] * rdi;
                ss = fmaf(fn[c], fn[c], ss);
            }
            float4* nd = (float4*)(Ndout + (size_t)i * 8);
            nd[0] = make_float4(fn[0], fn[1], fn[2], fn[3]);
            nd[1] = make_float4(fn[4], fn[5], fn[6], ss);
        }
    }
}

// ---------------- launch ----------------
extern "C" void kernel_launch(void* const* d_in, const int* in_sizes, int n_in,
                              void* d_out, int out_size) {
    const float *A = nullptr, *X = nullptr, *w1 = nullptr, *b1 = nullptr,
                *w2 = nullptr, *b2 = nullptr, *lg0 = nullptr, *raw = nullptr;
    for (int t = 0; t < n_in; t++) {
        int sz = in_sizes[t];
        const float* p = (const float*)d_in[t];
        if      (sz == NN * NN)        A  = p;
        else if (sz == NN * IN_DIM)    X  = p;
        else if (sz == IN_DIM * HID)   w1 = p;
        else if (sz == HID)            b1 = p;
        else if (sz == HID * OUT_DIM)  w2 = p;
        else if (sz == OUT_DIM)        b2 = p;
        else if (sz == 1) { if (!lg0) lg0 = p; else raw = p; }
    }
    float* out = (float*)d_out;

    fused_build_mlp1<<<256, 256>>>(A, X, w1, b1);
    mlp2_kernel<<<(NN + 255) / 256, 256>>>(w2, b2, lg0, raw);

    float *NdA, *NdB;
    cudaGetSymbolAddress((void**)&NdA, g_NdA);
    cudaGetSymbolAddress((void**)&NdB, g_NdB);

    for (int k = 0; k < K_STEPS; k++) {
        int last = (k == K_STEPS - 1) ? 1 : 0;
        const float* Ndin = (k & 1) ? NdB : NdA;
        float* Ndout = (k & 1) ? NdA : NdB;
        row_kernel<<<1024, 128>>>(k, last, Ndin, Ndout, out);
    }
}

// round 8
// speedup vs baseline: 1.2335x; 1.1611x over previous
#include <cuda_runtime.h>
#include <cuda_bf16.h>
#include <math.h>

#define NN 4096
#define IN_DIM 1433
#define HID 64
#define OUT_DIM 7
#define MAXDEG 160
#define SCAD_A 3.7f
#define LAMW ((float)(1.0/0.9 - 1.0))
#define K_STEPS 10
#define KT 32
#define NTILE ((IN_DIM + KT - 1) / KT)   // 45

// ---------------- device globals ----------------
__device__ float  g_F0[NN * 8];
__device__ float  g_NdA[NN * 8];          // {Fn[0..6], sq} ping
__device__ float  g_NdB[NN * 8];          // pong
__device__ float4 g_meta[NN];             // {rD, D, deg(bits), 0}
__device__ float  g_lam[K_STEPS];
__device__ int    g_cols[NN * MAXDEG];

typedef unsigned long long ull;

__device__ __forceinline__ ull pack_dup(float v) {
    ull r; asm("mov.b64 %0, {%1, %1};" : "=l"(r) : "f"(v)); return r;
}
__device__ __forceinline__ void fma2(ull& d, ull a, ull b) {
    asm("fma.rn.f32x2 %0, %1, %2, %0;" : "+l"(d) : "l"(a), "l"(b));
}
__device__ __forceinline__ void unpack2(ull p, float& lo, float& hi) {
    asm("mov.b64 {%0, %1}, %2;" : "=f"(lo), "=f"(hi) : "l"(p));
}

// ============================================================================
// Kernel 1: adjacency — one row per warp, 512 blocks x 256 threads
// ============================================================================
__global__ __launch_bounds__(256)
void build_adj(const float* __restrict__ A,
               const float* __restrict__ lg0p,
               const float* __restrict__ rawp) {
    int warp = threadIdx.x >> 5, lane = threadIdx.x & 31;
    int r = blockIdx.x * 8 + warp;
    const float4* row4 = (const float4*)(A + (size_t)r * NN);
    int* cols = g_cols + (size_t)r * MAXDEG;
    unsigned below = (1u << lane) - 1u;
    int cnt = 0;

    #pragma unroll 1
    for (int c0 = 0; c0 < NN; c0 += 256) {
        float4 va = row4[(c0 >> 2) + lane];          // cols c0+4*lane ..
        float4 vb = row4[(c0 >> 2) + 32 + lane];     // cols c0+128+4*lane ..
        unsigned mk = 0;
        mk |= (va.x != 0.0f) ? 1u   : 0u;
        mk |= (va.y != 0.0f) ? 2u   : 0u;
        mk |= (va.z != 0.0f) ? 4u   : 0u;
        mk |= (va.w != 0.0f) ? 8u   : 0u;
        mk |= (vb.x != 0.0f) ? 16u  : 0u;
        mk |= (vb.y != 0.0f) ? 32u  : 0u;
        mk |= (vb.z != 0.0f) ? 64u  : 0u;
        mk |= (vb.w != 0.0f) ? 128u : 0u;
        int c = __popc(mk);
        // bit-sliced cross-lane prefix (c in 0..8 -> 4 bits)
        int pre = 0, tot = 0;
        #pragma unroll
        for (int t = 0; t < 4; t++) {
            unsigned m = __ballot_sync(0xffffffffu, (c >> t) & 1);
            pre += __popc(m & below) << t;
            tot += __popc(m) << t;
        }
        int base = cnt + pre;
        cnt += tot;
        if (mk) {
            int cA = c0 + lane * 4, cB = c0 + 128 + lane * 4;
            if (mk & 1u)   { if (base < MAXDEG) cols[base] = cA + 0; base++; }
            if (mk & 2u)   { if (base < MAXDEG) cols[base] = cA + 1; base++; }
            if (mk & 4u)   { if (base < MAXDEG) cols[base] = cA + 2; base++; }
            if (mk & 8u)   { if (base < MAXDEG) cols[base] = cA + 3; base++; }
            if (mk & 16u)  { if (base < MAXDEG) cols[base] = cB + 0; base++; }
            if (mk & 32u)  { if (base < MAXDEG) cols[base] = cB + 1; base++; }
            if (mk & 64u)  { if (base < MAXDEG) cols[base] = cB + 2; base++; }
            if (mk & 128u) { if (base < MAXDEG) cols[base] = cB + 3; base++; }
        }
    }
    if (lane == 0) {
        int d = cnt < MAXDEG ? cnt : MAXDEG;
        float D = (float)cnt + 1.0f;    // self loop
        g_meta[r] = make_float4(1.0f / sqrtf(D), D, __int_as_float(d), 0.0f);
    }
    if (blockIdx.x == 0 && threadIdx.x == 0) {
        float g0 = expf(lg0p[0]);
        float rr = 1.0f / (1.0f + expf(-rawp[0]));
        float gk = g0;
        #pragma unroll
        for (int k = 0; k < K_STEPS; k++) { g_lam[k] = gk / SCAD_A; gk *= rr; }
    }
}

// ============================================================================
// Kernel 2: mlp_fused — H = relu(X@w1+b1) in smem; F0 = H@w2+b2; Nd seed
// 128 blocks x 256 threads, 32 rows per block
// ============================================================================
__global__ __launch_bounds__(256, 2)
void mlp_fused(const float* __restrict__ X,
               const float* __restrict__ w1,
               const float* __restrict__ b1,
               const float* __restrict__ w2,
               const float* __restrict__ b2) {
    __shared__ __align__(16) ull   Xd[2][KT][33];    // duplicated X (x,x)
    __shared__ __align__(16) float Wsm[2][KT][HID];
    __shared__ float Hs[32][65];
    __shared__ float F0s[32][8];
    __shared__ float w2s[HID * OUT_DIM];
    __shared__ float b2s[OUT_DIM];
    int tid = threadIdx.x;
    int m0 = blockIdx.x * 32;
    int tx = tid & 15;           // col group c0 = tx*4
    int ty = tid >> 4;           // rows ty*2, ty*2+1
    ull acc[2][2] = {{0ull, 0ull}, {0ull, 0ull}};

    // stage w2/b2 (STRIDED: HID*OUT_DIM = 448 > blockDim = 256)
    for (int idx = tid; idx < HID * OUT_DIM; idx += 256) w2s[idx] = w2[idx];
    if (tid >= 256 - OUT_DIM) b2s[tid - (256 - OUT_DIM)] = b2[tid - (256 - OUT_DIM)];

    // X staged scalar (IN_DIM=1433 odd -> rows only 4B aligned)
    float xr0, xr1, xr2, xr3;
    int xrow = tid >> 3;
    int xk   = (tid & 7) * 4;
    float4 wr[2];
    const float* xrow_p = X + (size_t)(m0 + xrow) * IN_DIM;
    {
        xr0 = xrow_p[xk + 0]; xr1 = xrow_p[xk + 1];
        xr2 = xrow_p[xk + 2]; xr3 = xrow_p[xk + 3];
        #pragma unroll
        for (int j = 0; j < 2; j++) {
            int f4 = tid + j * 256;
            int k = f4 >> 4, n4 = f4 & 15;
            wr[j] = *(const float4*)(w1 + (size_t)k * HID + n4 * 4);
        }
    }

    for (int t = 0; t < NTILE; t++) {
        int buf = t & 1;
        __syncthreads();
        Xd[buf][xk + 0][xrow] = pack_dup(xr0);
        Xd[buf][xk + 1][xrow] = pack_dup(xr1);
        Xd[buf][xk + 2][xrow] = pack_dup(xr2);
        Xd[buf][xk + 3][xrow] = pack_dup(xr3);
        #pragma unroll
        for (int j = 0; j < 2; j++) {
            int f4 = tid + j * 256;
            int k = f4 >> 4, n4 = f4 & 15;
            *(float4*)&Wsm[buf][k][n4 * 4] = wr[j];
        }
        if (t + 1 < NTILE) {
            int kt = (t + 1) * KT;
            if (kt + KT <= IN_DIM) {
                xr0 = xrow_p[kt + xk + 0]; xr1 = xrow_p[kt + xk + 1];
                xr2 = xrow_p[kt + xk + 2]; xr3 = xrow_p[kt + xk + 3];
                #pragma unroll
                for (int j = 0; j < 2; j++) {
                    int f4 = tid + j * 256;
                    int k = kt + (f4 >> 4), n4 = f4 & 15;
                    wr[j] = *(const float4*)(w1 + (size_t)k * HID + n4 * 4);
                }
            } else {
                xr0 = (kt + xk + 0 < IN_DIM) ? xrow_p[kt + xk + 0] : 0.0f;
                xr1 = (kt + xk + 1 < IN_DIM) ? xrow_p[kt + xk + 1] : 0.0f;
                xr2 = (kt + xk + 2 < IN_DIM) ? xrow_p[kt + xk + 2] : 0.0f;
                xr3 = (kt + xk + 3 < IN_DIM) ? xrow_p[kt + xk + 3] : 0.0f;
                #pragma unroll
                for (int j = 0; j < 2; j++) {
                    int f4 = tid + j * 256;
                    int k = kt + (f4 >> 4), n4 = f4 & 15;
                    wr[j] = (k < IN_DIM)
                          ? *(const float4*)(w1 + (size_t)k * HID + n4 * 4)
                          : make_float4(0.f, 0.f, 0.f, 0.f);
                }
            }
        }
        __syncthreads();
        #pragma unroll
        for (int k = 0; k < KT; k++) {
            ull ar0 = Xd[buf][k][ty * 2];
            ull ar1 = Xd[buf][k][ty * 2 + 1];
            ulonglong2 b = *(const ulonglong2*)&Wsm[buf][k][tx * 4];
            fma2(acc[0][0], ar0, b.x);
            fma2(acc[0][1], ar0, b.y);
            fma2(acc[1][0], ar1, b.x);
            fma2(acc[1][1], ar1, b.y);
        }
    }

    // H tile -> smem (with bias + relu)
    float4 bv = *(const float4*)&b1[tx * 4];
    #pragma unroll
    for (int r = 0; r < 2; r++) {
        int rl = ty * 2 + r;
        float o0, o1, o2, o3;
        unpack2(acc[r][0], o0, o1);
        unpack2(acc[r][1], o2, o3);
        Hs[rl][tx * 4 + 0] = fmaxf(o0 + bv.x, 0.0f);
        Hs[rl][tx * 4 + 1] = fmaxf(o1 + bv.y, 0.0f);
        Hs[rl][tx * 4 + 2] = fmaxf(o2 + bv.z, 0.0f);
        Hs[rl][tx * 4 + 3] = fmaxf(o3 + bv.w, 0.0f);
    }
    __syncthreads();

    // mlp2: 224 threads, one (row, out) each
    if (tid < 32 * OUT_DIM) {
        int o = tid >> 5, r = tid & 31;
        float a = b2s[o];
        #pragma unroll 16
        for (int k = 0; k < HID; k++) a = fmaf(Hs[r][k], w2s[k * OUT_DIM + o], a);
        F0s[r][o] = a;
    }
    __syncthreads();

    // F0 + Nd seed: one thread per row
    if (tid < 32) {
        int row = m0 + tid;
        float rd = g_meta[row].x;
        float fn[7], ss = 0.0f;
        #pragma unroll
        for (int o = 0; o < 7; o++) {
            float v = F0s[tid][o];
            g_F0[row * 8 + o] = v;
            fn[o] = v * rd;
            ss = fmaf(fn[o], fn[o], ss);
        }
        g_F0[row * 8 + 7] = 0.0f;
        float4* nd = (float4*)(g_NdA + (size_t)row * 8);
        nd[0] = make_float4(fn[0], fn[1], fn[2], fn[3]);
        nd[1] = make_float4(fn[4], fn[5], fn[6], ss);
    }
}

// ============================================================================
// Kernel 3: sparse row update — 8 lanes per row, 128 blocks x 256 threads
// ============================================================================
__device__ __forceinline__ float shx(float v, int m) {
    return __shfl_xor_sync(0xffffffffu, v, m);
}

__global__ __launch_bounds__(256)
void row_kernel(int kstep, int last,
                const float* __restrict__ Ndin,
                float* __restrict__ Ndout,
                float* __restrict__ out) {
    int gid = blockIdx.x * 256 + threadIdx.x;
    int i = gid >> 3;                 // row
    int g = threadIdx.x & 7;          // group lane

    float lam = g_lam[kstep];
    float alam = SCAD_A * lam;
    float4 meta = g_meta[i];          // broadcast within group
    float rdi = meta.x, Di = meta.y;
    int deg = __float_as_int(meta.z);
    float F0g = __ldg(&g_F0[(size_t)i * 8 + g]);   // slot 7 = 0
    const float4* ndi = (const float4*)(Ndin + (size_t)i * 8);
    float4 f0 = __ldg(ndi), f1 = __ldg(ndi + 1);
    float fni[7] = {f0.x, f0.y, f0.z, f0.w, f1.x, f1.y, f1.z};
    float sqi = f1.w;
    const int4* c4 = (const int4*)(g_cols + (size_t)i * MAXDEG);

    float t0 = 0.f, t1 = 0.f, t2 = 0.f, t3 = 0.f,
          t4 = 0.f, t5 = 0.f, t6 = 0.f, t7 = 0.f;   // t7 = s

    for (int base = 0; base < deg; base += 32) {
        int4 cc = c4[(base >> 2) + g];
        int e0 = base + g * 4;
        int jj[4] = {cc.x, cc.y, cc.z, cc.w};
        #pragma unroll
        for (int q = 0; q < 4; q++) {
            if (e0 + q < deg) {
                int j = jj[q];
                const float4* nj = (const float4*)(Ndin + (size_t)j * 8);
                float4 a0 = __ldg(nj), a1 = __ldg(nj + 1);
                float dot = fni[0] * a0.x + fni[1] * a0.y + fni[2] * a0.z
                          + fni[3] * a0.w + fni[4] * a1.x + fni[5] * a1.y
                          + fni[6] * a1.z;
                float Z = fmaxf(sqi + a1.w - 2.0f * dot, 0.0f);
                float y = sqrtf(Z);
                float w;
                if (y <= lam)        w = 1.0f;
                else if (y <= alam)  w = __fdividef(alam - y,
                                                    (SCAD_A - 1.0f) * fmaxf(y, 1e-12f));
                else                 w = 0.0f;
                t7 += w;
                t0 = fmaf(w, a0.x, t0);
                t1 = fmaf(w, a0.y, t1);
                t2 = fmaf(w, a0.z, t2);
                t3 = fmaf(w, a0.w, t3);
                t4 = fmaf(w, a1.x, t4);
                t5 = fmaf(w, a1.y, t5);
                t6 = fmaf(w, a1.z, t6);
            }
        }
    }

    // transposing tree reduce over the 8-lane group: lane g ends with sum of comp g
    bool h4 = (g & 4) != 0, h2 = (g & 2) != 0, h1 = (g & 1) != 0;
    float r0 = shx(h4 ? t0 : t4, 4);
    float r1 = shx(h4 ? t1 : t5, 4);
    float r2 = shx(h4 ? t2 : t6, 4);
    float r3 = shx(h4 ? t3 : t7, 4);
    float u0 = (h4 ? t4 : t0) + r0;
    float u1 = (h4 ? t5 : t1) + r1;
    float u2 = (h4 ? t6 : t2) + r2;
    float u3 = (h4 ? t7 : t3) + r3;
    r0 = shx(h2 ? u0 : u2, 2);
    r1 = shx(h2 ? u1 : u3, 2);
    float w0 = (h2 ? u2 : u0) + r0;
    float w1 = (h2 ? u3 : u1) + r1;
    r0 = shx(h1 ? w0 : w1, 1);
    float tot = (h1 ? w1 : w0) + r0;

    float sT = __shfl_sync(0xffffffffu, tot, 7, 8);   // comp 7 = s
    float Q = sT / Di + LAMW;
    float invQ = 1.0f / Q;
    float f = (rdi * tot + LAMW * F0g) * invQ;

    if (last) {
        if (g < 7) out[(size_t)i * OUT_DIM + g] = f;
    } else {
        float fn = f * rdi;
        float c = (g < 7) ? fn * fn : 0.0f;
        c += shx(c, 1);
        c += shx(c, 2);
        c += shx(c, 4);
        Ndout[(size_t)i * 8 + g] = (g < 7) ? fn : c;
    }
}

// ---------------- launch ----------------
extern "C" void kernel_launch(void* const* d_in, const int* in_sizes, int n_in,
                              void* d_out, int out_size) {
    const float *A = nullptr, *X = nullptr, *w1 = nullptr, *b1 = nullptr,
                *w2 = nullptr, *b2 = nullptr, *lg0 = nullptr, *raw = nullptr;
    for (int t = 0; t < n_in; t++) {
        int sz = in_sizes[t];
        const float* p = (const float*)d_in[t];
        if      (sz == NN * NN)        A  = p;
        else if (sz == NN * IN_DIM)    X  = p;
        else if (sz == IN_DIM * HID)   w1 = p;
        else if (sz == HID)            b1 = p;
        else if (sz == HID * OUT_DIM)  w2 = p;
        else if (sz == OUT_DIM)        b2 = p;
        else if (sz == 1) { if (!lg0) lg0 = p; else raw = p; }
    }
    float* out = (float*)d_out;

    build_adj<<<512, 256>>>(A, lg0, raw);
    mlp_fused<<<128, 256>>>(X, w1, b1, w2, b2);

    float *NdA, *NdB;
    cudaGetSymbolAddress((void**)&NdA, g_NdA);
    cudaGetSymbolAddress((void**)&NdB, g_NdB);

    for (int k = 0; k < K_STEPS; k++) {
        int last = (k == K_STEPS - 1) ? 1 : 0;
        const float* Ndin = (k & 1) ? NdB : NdA;
        float* Ndout = (k & 1) ? NdA : NdB;
        row_kernel<<<128, 256>>>(k, last, Ndin, Ndout, out);
    }
}